// round 9
// baseline (speedup 1.0000x reference)
#include <cuda_runtime.h>
#include <cuda_fp16.h>
#include <cstdint>

// ---------------------------------------------------------------------------
// GCN via mma.sync fp16 GEMMs (fp32 accumulate).
//   GEMM1: H^T[256][32768] = W^T @ X^T  -> fp16
//   GEMM2: Out[b] = adj @ H_b           -> fp32
// R9: B-fragment software pipelining (double-buffered ldmatrix for both A and
//     B), single __syncthreads per stage with early prefetch, wider cvt grid.
// ---------------------------------------------------------------------------

#define N_NODES 512
#define N_BATCH 64
#define D_IN    256
#define D_OUT   256
#define M_ALL   (N_NODES * N_BATCH)   // 32768

#define BM 128
#define BN 128
#define BKB 64                        // fp16 k per stage
#define NTHREADS 256
#define S_STAGES 3
#define PITCHB 144                    // 128B row + 16B pad -> ldsm conflict-free
#define TILEB (128 * PITCHB)          // 18432 per matrix
#define STAGEB (2 * TILEB)            // 36864
#define SMEM_TOTAL (S_STAGES * STAGEB) // 110592
#define OFF_A 0
#define OFF_B TILEB

// device scratch
__device__ __half g_xh[(size_t)M_ALL * D_IN];
__device__ __half g_wth[D_OUT * D_IN];
__device__ __half g_adjh[N_NODES * N_NODES];
__device__ __half g_h[(size_t)D_OUT * M_ALL];

// ---------------- helpers ----------------
__device__ __forceinline__ uint32_t smem_u32(const void* p) {
    uint32_t a;
    asm("{ .reg .u64 t; cvta.to.shared.u64 t, %1; cvt.u32.u64 %0, t; }" : "=r"(a) : "l"(p));
    return a;
}
__device__ __forceinline__ void cp16(uint32_t dst, const void* src) {
    asm volatile("cp.async.cg.shared.global [%0], [%1], 16;" :: "r"(dst), "l"(src) : "memory");
}
__device__ __forceinline__ void cp_commit() {
    asm volatile("cp.async.commit_group;" ::: "memory");
}
template <int N>
__device__ __forceinline__ void cp_wait() {
    asm volatile("cp.async.wait_group %0;" :: "n"(N) : "memory");
}
__device__ __forceinline__ void ldsm_x4(uint32_t* r, uint32_t addr) {
    asm volatile("ldmatrix.sync.aligned.m8n8.x4.shared.b16 {%0,%1,%2,%3}, [%4];"
                 : "=r"(r[0]), "=r"(r[1]), "=r"(r[2]), "=r"(r[3]) : "r"(addr));
}
__device__ __forceinline__ void mma_f16(float* c, const uint32_t* a, const uint32_t* b) {
    asm volatile(
        "mma.sync.aligned.m16n8k16.row.col.f32.f16.f16.f32 "
        "{%0,%1,%2,%3}, {%4,%5,%6,%7}, {%8,%9}, {%0,%1,%2,%3};"
        : "+f"(c[0]), "+f"(c[1]), "+f"(c[2]), "+f"(c[3])
        : "r"(a[0]), "r"(a[1]), "r"(a[2]), "r"(a[3]), "r"(b[0]), "r"(b[1]));
}

// ---------------- merged convert kernel ----------------
// blocks [0,1024): x | [1024,1056): adj | [1056,1312): w transpose
__global__ __launch_bounds__(256) void cvt_all(const float* __restrict__ x,
                                               const float* __restrict__ adj,
                                               const float* __restrict__ w,
                                               __half* __restrict__ xh,
                                               __half* __restrict__ adjh,
                                               __half* __restrict__ wth) {
    const int b = blockIdx.x;
    if (b < 1024) {
        const int n8 = M_ALL * D_IN / 8;   // 1048576
        int i = b * 256 + threadIdx.x;
        const int stride = 1024 * 256;
        for (; i < n8; i += stride) {
            float4 a = ((const float4*)x)[2 * i];
            float4 c = ((const float4*)x)[2 * i + 1];
            __half2 h0 = __float22half2_rn(make_float2(a.x, a.y));
            __half2 h1 = __float22half2_rn(make_float2(a.z, a.w));
            __half2 h2 = __float22half2_rn(make_float2(c.x, c.y));
            __half2 h3 = __float22half2_rn(make_float2(c.z, c.w));
            uint4 v = {*(uint32_t*)&h0, *(uint32_t*)&h1, *(uint32_t*)&h2, *(uint32_t*)&h3};
            ((uint4*)xh)[i] = v;
        }
    } else if (b < 1056) {
        const int n8 = N_NODES * N_NODES / 8;  // 32768
        int i = (b - 1024) * 256 + threadIdx.x;
        const int stride = 32 * 256;
        for (; i < n8; i += stride) {
            float4 a = ((const float4*)adj)[2 * i];
            float4 c = ((const float4*)adj)[2 * i + 1];
            __half2 h0 = __float22half2_rn(make_float2(a.x, a.y));
            __half2 h1 = __float22half2_rn(make_float2(a.z, a.w));
            __half2 h2 = __float22half2_rn(make_float2(c.x, c.y));
            __half2 h3 = __float22half2_rn(make_float2(c.z, c.w));
            uint4 v = {*(uint32_t*)&h0, *(uint32_t*)&h1, *(uint32_t*)&h2, *(uint32_t*)&h3};
            ((uint4*)adjh)[i] = v;
        }
    } else {
        int o = b - 1056;           // 0..255
        int i = threadIdx.x;        // 0..255
        wth[o * D_IN + i] = __float2half_rn(w[i * D_OUT + o]);
    }
}

// ---------------- main GEMM: C = A * B^T (both K-major, fp16) ----------------
template <bool HALF_OUT>
__global__ __launch_bounds__(NTHREADS, 2)
void hgemm_f16(const __half* __restrict__ A, int lda,
               const __half* __restrict__ B, int ldb, long bStride,
               __half* __restrict__ Ch, float* __restrict__ Cf,
               int ldc, long cStride, int K) {
    extern __shared__ char smem[];
    const uint32_t sb = smem_u32(smem);
    const int tid = threadIdx.x;
    const int lane = tid & 31;
    const int wid = tid >> 5;
    const int wm = (wid & 3) * 32;   // warp m offset
    const int wn = (wid >> 2) * 64;  // warp n offset

    const int m0 = blockIdx.y * BM;
    const int n0 = blockIdx.x * BN;
    const long bz = blockIdx.z;
    B += bz * bStride;

    // cp.async coords: per matrix 128 rows x 8 chunks of 16B; 4 chunks/thread
    const int cr = tid >> 3;          // base row 0..31 (+32 per j)
    const int cc = tid & 7;           // 16B chunk in row
    const uint32_t soBase = (uint32_t)(cc * 16);
    const int gcol = cc * 8;          // halves

    // ldmatrix addresses (conflict-free: PITCHB mod 128 = 16)
    const uint32_t aOff = (uint32_t)((wm + (lane & 15)) * PITCHB + ((lane >> 4) << 4));
    const uint32_t bOff = (uint32_t)((wn + ((lane >> 4) << 3) + (lane & 7)) * PITCHB +
                                     (((lane >> 3) & 1) << 4));

    float acc[2][8][4];
#pragma unroll
    for (int mt = 0; mt < 2; mt++)
#pragma unroll
        for (int nt = 0; nt < 8; nt++)
#pragma unroll
            for (int q = 0; q < 4; q++) acc[mt][nt][q] = 0.0f;

    const int NT = K / BKB;

    auto load_stage = [&](int t) {
        const uint32_t st = sb + (uint32_t)((t % S_STAGES) * STAGEB);
        const int k0 = t * BKB + gcol;
#pragma unroll
        for (int j = 0; j < 4; j++) {
            int r = cr + j * 32;
            uint32_t so = (uint32_t)(r * PITCHB) + soBase;
            cp16(st + OFF_A + so, A + (size_t)(m0 + r) * lda + k0);
            cp16(st + OFF_B + so, B + (size_t)(n0 + r) * ldb + k0);
        }
        cp_commit();
    };

    load_stage(0);
    if (NT > 1) load_stage(1);

    uint32_t ah[2][2][4];   // [buf][mt][frag]
    uint32_t bh[2][4];      // [buf][frag]

    for (int t = 0; t < NT; t++) {
        cp_wait<1>();
        __syncthreads();

        // prefetch stage t+2 into slot (t+2)%3 == slot of stage t-1 (fully
        // consumed: the barrier above proves every warp finished iteration
        // t-1's reads). Commit every iteration to keep wait_group<1> aligned.
        if (t + 2 < NT) {
            load_stage(t + 2);
        } else {
            cp_commit();
        }

        const uint32_t st = sb + (uint32_t)((t % S_STAGES) * STAGEB);
        const uint32_t aBase = st + OFF_A + aOff;
        const uint32_t bBase = st + OFF_B + bOff;

        // preload ko=0 A frags and step-0 B frag
#pragma unroll
        for (int mt = 0; mt < 2; mt++)
            ldsm_x4(ah[0][mt], aBase + mt * 16 * PITCHB);
        ldsm_x4(bh[0], bBase);

        // 16 steps: i = ko*4 + np, B frags double-buffered across steps,
        // A frags double-buffered across ko.
#pragma unroll
        for (int i = 0; i < 16; i++) {
            const int ko = i >> 2, np = i & 3;
            const int bcur = i & 1;
            if (i < 15) {
                const int ni = i + 1;
                const int nko = ni >> 2, nnp = ni & 3;
                ldsm_x4(bh[bcur ^ 1], bBase + nnp * 16 * PITCHB + nko * 32);
            }
            if (np == 0 && ko < 3) {
#pragma unroll
                for (int mt = 0; mt < 2; mt++)
                    ldsm_x4(ah[(ko + 1) & 1][mt], aBase + mt * 16 * PITCHB + (ko + 1) * 32);
            }
#pragma unroll
            for (int sub = 0; sub < 2; sub++)
#pragma unroll
                for (int mt = 0; mt < 2; mt++)
                    mma_f16(acc[mt][np * 2 + sub], ah[ko & 1][mt], bh[bcur] + sub * 2);
        }
    }

    // epilogue
    const int l4 = lane >> 2;
    const int lp = lane & 3;
#pragma unroll
    for (int mt = 0; mt < 2; mt++) {
#pragma unroll
        for (int nt = 0; nt < 8; nt++) {
            const float* c = acc[mt][nt];
            long m = m0 + wm + mt * 16 + l4;
            long n = n0 + wn + nt * 8 + lp * 2;
            if (HALF_OUT) {
                __half2 p0 = __float22half2_rn(make_float2(c[0], c[1]));
                __half2 p1 = __float22half2_rn(make_float2(c[2], c[3]));
                *(uint32_t*)(Ch + m * ldc + n) = *(uint32_t*)&p0;
                *(uint32_t*)(Ch + (m + 8) * ldc + n) = *(uint32_t*)&p1;
            } else {
                float* base = Cf + bz * cStride;
                *(float2*)(base + m * ldc + n) = make_float2(c[0], c[1]);
                *(float2*)(base + (m + 8) * ldc + n) = make_float2(c[2], c[3]);
            }
        }
    }
}

// ---------------- launch ----------------
extern "C" void kernel_launch(void* const* d_in, const int* in_sizes, int n_in,
                              void* d_out, int out_size) {
    const float* x      = (const float*)d_in[0];
    const float* weight = (const float*)d_in[2];
    const float* adj    = (const float*)d_in[3];
    float* out          = (float*)d_out;

    __half *xh, *wth, *adjh, *h;
    cudaGetSymbolAddress((void**)&xh, g_xh);
    cudaGetSymbolAddress((void**)&wth, g_wth);
    cudaGetSymbolAddress((void**)&adjh, g_adjh);
    cudaGetSymbolAddress((void**)&h, g_h);

    cudaFuncSetAttribute(hgemm_f16<true>, cudaFuncAttributeMaxDynamicSharedMemorySize, SMEM_TOTAL);
    cudaFuncSetAttribute(hgemm_f16<false>, cudaFuncAttributeMaxDynamicSharedMemorySize, SMEM_TOTAL);

    cvt_all<<<1312, 256>>>(x, adj, weight, xh, adjh, wth);

    // GEMM1: H^T = W^T @ X^T ; A=W^T [256][256], B=X [32768][256] -> H^T fp16
    {
        dim3 grid(M_ALL / BN, D_OUT / BM, 1);
        hgemm_f16<true><<<grid, NTHREADS, SMEM_TOTAL>>>(
            wth, D_IN,
            xh, D_IN, 0L,
            h, nullptr, M_ALL, 0L,
            D_IN);
    }
    // GEMM2: Out[b] = adj @ H_b ; A=adj [512][512], B=H^T col-slice b*512
    {
        dim3 grid(D_OUT / BN, N_NODES / BM, N_BATCH);
        hgemm_f16<false><<<grid, NTHREADS, SMEM_TOTAL>>>(
            adjh, N_NODES,
            h, M_ALL, (long)N_NODES,
            nullptr, out, D_OUT, (long)(N_NODES * D_OUT),
            N_NODES);
    }
}